// round 7
// baseline (speedup 1.0000x reference)
#include <cuda_runtime.h>
#include <cstdint>
#include <math.h>

#define BLOCKT  64           // 2 warps per block; warp owns 32 samples
#define KDIM    784
#define KPAD    800
#define TILE_K  32
#define NT      25           // 25*32 = 800 (zero-filled past 784)
#define XSTRIDE 36           // 32 + 4 pad -> conflict-free LDS/STS.128
#define STAGE   (32*XSTRIDE) // 1152 floats: one warp's 32-row tile
#define STAGES  2

// smem floats: xs[2 warps][2][STAGE] + w1s[800*4] + sw[240] = 8048 floats = 31.4KB
#define SMEM_FLOATS (2*STAGES*STAGE + KPAD*4 + 240)

__device__ __forceinline__ float4 ldcg4(const float* p) {
    float4 v;
    asm volatile("ld.global.cg.v4.f32 {%0,%1,%2,%3}, [%4];"
                 : "=f"(v.x), "=f"(v.y), "=f"(v.z), "=f"(v.w) : "l"(p));
    return v;
}

__global__ void __launch_bounds__(BLOCKT) qhybrid_kernel(
    const float* __restrict__ x,
    const float* __restrict__ W1, const float* __restrict__ b1,
    const float* __restrict__ qw,
    const float* __restrict__ W2, const float* __restrict__ b2,
    const float* __restrict__ W3, const float* __restrict__ b3,
    float* __restrict__ out, int B)
{
    extern __shared__ float smem[];
    float* xs  = smem;                       // [2][2][32][36]
    float* w1s = smem + 2 * STAGES * STAGE;  // [800][4]
    float* sw  = w1s + KPAD * 4;             // small weights

    const int tid  = threadIdx.x;
    const int lane = tid & 31;
    const int wrp  = tid >> 5;               // 0..1
    const int rr   = lane >> 3;              // staging row group 0..3
    const int cc   = lane & 7;               // col chunk 0..7

    const long sbase = (long)blockIdx.x * BLOCKT + wrp * 32;  // warp's first sample
    const float* srow0 = x + (sbase + rr) * (long)KDIM;       // staging base row

    float* wbuf = xs + wrp * STAGES * STAGE;
    float* sdst0 = wbuf + rr * XSTRIDE + cc * 4;

    // row validity for the 8 staging rows (rr + 4i)
    bool rok[8];
    #pragma unroll
    for (int i = 0; i < 8; i++)
        rok[i] = (sbase + rr + 4 * i < (long)B);

    // ---- register staging loaders (tile kp -> 8 float4) ----
    #define LOAD_TILE(V, kp) do {                                            \
        const int _col = (kp) * TILE_K + cc * 4;                             \
        const bool _cok = (_col < KDIM);                                     \
        _Pragma("unroll")                                                    \
        for (int _i = 0; _i < 8; _i++) {                                     \
            if (_cok && rok[_i]) V[_i] = ldcg4(srow0 + (long)_i*4*KDIM + _col); \
            else                 V[_i] = make_float4(0.f,0.f,0.f,0.f);       \
        }                                                                    \
    } while (0)

    #define STS_TILE(V, kt) do {                                             \
        float* _d = sdst0 + ((kt) & 1) * STAGE;                              \
        _Pragma("unroll")                                                    \
        for (int _i = 0; _i < 8; _i++)                                       \
            *(float4*)(_d + _i * 4 * XSTRIDE) = V[_i];                       \
    } while (0)

    #define COMPUTE_TILE(kt) do {                                            \
        const float* _xr = wbuf + ((kt) & 1) * STAGE + lane * XSTRIDE;       \
        const int _cb = (kt) * TILE_K;                                       \
        _Pragma("unroll")                                                    \
        for (int _jj = 0; _jj < 8; _jj++) {                                  \
            float4 _xv = *(const float4*)(_xr + _jj * 4);                    \
            const float* _wp = w1s + (_cb + _jj * 4) * 4;                    \
            float4 _wa = *(const float4*)(_wp);                              \
            float4 _wb = *(const float4*)(_wp + 4);                          \
            float4 _wc = *(const float4*)(_wp + 8);                          \
            float4 _wd = *(const float4*)(_wp + 12);                         \
            acc[0]=fmaf(_xv.x,_wa.x,acc[0]); acc[1]=fmaf(_xv.x,_wa.y,acc[1]);\
            acc[2]=fmaf(_xv.x,_wa.z,acc[2]); acc[3]=fmaf(_xv.x,_wa.w,acc[3]);\
            acc[0]=fmaf(_xv.y,_wb.x,acc[0]); acc[1]=fmaf(_xv.y,_wb.y,acc[1]);\
            acc[2]=fmaf(_xv.y,_wb.z,acc[2]); acc[3]=fmaf(_xv.y,_wb.w,acc[3]);\
            acc[0]=fmaf(_xv.z,_wc.x,acc[0]); acc[1]=fmaf(_xv.z,_wc.y,acc[1]);\
            acc[2]=fmaf(_xv.z,_wc.z,acc[2]); acc[3]=fmaf(_xv.z,_wc.w,acc[3]);\
            acc[0]=fmaf(_xv.w,_wd.x,acc[0]); acc[1]=fmaf(_xv.w,_wd.y,acc[1]);\
            acc[2]=fmaf(_xv.w,_wd.z,acc[2]); acc[3]=fmaf(_xv.w,_wd.w,acc[3]);\
        }                                                                    \
    } while (0)

    float4 va[8], vb[8];

    // ---- prologue: tiles 0 and 1 in flight in registers ----
    LOAD_TILE(va, 0);
    LOAD_TILE(vb, 1);

    // ---- preload W1 (zero-padded rows 784..799) + small weights ----
    for (int r = tid; r < KPAD; r += BLOCKT) {
        float4 v = make_float4(0.f, 0.f, 0.f, 0.f);
        if (r < KDIM) v = __ldg((const float4*)W1 + r);
        ((float4*)w1s)[r] = v;
    }
    // b1@0(4) qw@4(8) W2@12(128) b2@140(32) W3@172(64) b3@236(2)
    if (tid < 4)  sw[tid]      = b1[tid];
    if (tid < 8)  sw[4 + tid]  = qw[tid];
    for (int j = tid; j < 128; j += BLOCKT) sw[12 + j] = W2[j];
    if (tid < 32) sw[140 + tid] = b2[tid];
    for (int j = tid; j < 64; j += BLOCKT)  sw[172 + j] = W3[j];
    if (tid < 2)  sw[236 + tid] = b3[tid];
    __syncthreads();   // the ONLY block barrier: publish w1s/sw

    float acc[4] = {0.f, 0.f, 0.f, 0.f};

    // ---- GEMM mainloop: 2-deep register pipeline, warp-autonomous ----
    #pragma unroll 1
    for (int kt = 0; kt < NT - 1; kt += 2) {
        // even half: tile kt (in va)
        STS_TILE(va, kt);
        __syncwarp();
        if (kt + 2 < NT) LOAD_TILE(va, kt + 2);
        COMPUTE_TILE(kt);
        // odd half: tile kt+1 (in vb)
        STS_TILE(vb, kt + 1);
        __syncwarp();
        if (kt + 3 < NT) LOAD_TILE(vb, kt + 3);
        COMPUTE_TILE(kt + 1);
    }
    // tail: tile 24 (NT odd, sits in va)
    STS_TILE(va, NT - 1);
    __syncwarp();
    COMPUTE_TILE(NT - 1);

    // ---- angles = relu(pre + b1) ----
    float cq[4], sq[4];
    #pragma unroll
    for (int q = 0; q < 4; q++) {
        float ang = fmaxf(acc[q] + sw[q], 0.f);
        __sincosf(0.5f * ang, &sq[q], &cq[q]);
    }

    // ---- 4-qubit statevector in registers ----
    float re[16], im[16];
    #pragma unroll
    for (int i = 0; i < 16; i++) {
        float m = 1.f;
        #pragma unroll
        for (int q = 0; q < 4; q++) m *= ((i >> (3 - q)) & 1) ? sq[q] : cq[q];
        int k = __popc(i) & 3;  // phase (-i)^k
        re[i] = (k == 0) ? m : ((k == 2) ? -m : 0.f);
        im[i] = (k == 1) ? -m : ((k == 3) ? m : 0.f);
    }

    // ---- BasicEntanglerLayers: RX(w[l,q]) then CNOT ring ----
    #pragma unroll
    for (int l = 0; l < 2; l++) {
        #pragma unroll
        for (int q = 0; q < 4; q++) {
            float cg, sg;
            __sincosf(0.5f * sw[4 + l * 4 + q], &sg, &cg);
            const int mask = 8 >> q;
            #pragma unroll
            for (int i = 0; i < 16; i++) {
                if (i & mask) continue;
                const int i1 = i | mask;
                float r0 = re[i], ii0 = im[i], r1 = re[i1], ii1 = im[i1];
                re[i]  = fmaf(cg, r0,  sg * ii1);
                im[i]  = fmaf(cg, ii0, -sg * r1);
                re[i1] = fmaf(cg, r1,  sg * ii0);
                im[i1] = fmaf(cg, ii1, -sg * r0);
            }
        }
        #pragma unroll
        for (int q = 0; q < 4; q++) {
            const int cmask = 8 >> q;
            const int tmask = 8 >> ((q + 1) & 3);
            #pragma unroll
            for (int i = 0; i < 16; i++) {
                if ((i & cmask) && !(i & tmask)) {
                    const int j = i | tmask;
                    float t = re[i]; re[i] = re[j]; re[j] = t;
                    t = im[i]; im[i] = im[j]; im[j] = t;
                }
            }
        }
    }

    // ---- <Z_q> expectation values ----
    float ez[4] = {0.f, 0.f, 0.f, 0.f};
    #pragma unroll
    for (int i = 0; i < 16; i++) {
        float p = re[i] * re[i] + im[i] * im[i];
        #pragma unroll
        for (int q = 0; q < 4; q++)
            ez[q] += ((i >> (3 - q)) & 1) ? -p : p;
    }
    #pragma unroll
    for (int q = 0; q < 4; q++)
        if (!(ez[q] == ez[q])) ez[q] = 0.f;  // NaN -> 0 (matches reference)

    // ---- post = relu(ez@W2 + b2); logits = post@W3 + b3; softmax ----
    float l0 = sw[236], l1 = sw[237];
    #pragma unroll
    for (int j = 0; j < 32; j++) {
        float pj = sw[140 + j];
        #pragma unroll
        for (int q = 0; q < 4; q++)
            pj = fmaf(ez[q], sw[12 + q * 32 + j], pj);
        pj = fmaxf(pj, 0.f);
        l0 = fmaf(pj, sw[172 + j * 2],     l0);
        l1 = fmaf(pj, sw[172 + j * 2 + 1], l1);
    }
    float mx = fmaxf(l0, l1);
    float e0 = __expf(l0 - mx);
    float e1 = __expf(l1 - mx);
    float inv = 1.f / (e0 + e1);

    long sg = sbase + lane;
    if (sg < (long)B) {
        float2 o = make_float2(e0 * inv, e1 * inv);
        *(float2*)(out + sg * 2) = o;
    }
}

extern "C" void kernel_launch(void* const* d_in, const int* in_sizes, int n_in,
                              void* d_out, int out_size) {
    const float* x  = (const float*)d_in[0];
    const float* W1 = (const float*)d_in[1];
    const float* b1 = (const float*)d_in[2];
    const float* qw = (const float*)d_in[3];
    const float* W2 = (const float*)d_in[4];
    const float* b2 = (const float*)d_in[5];
    const float* W3 = (const float*)d_in[6];
    const float* b3 = (const float*)d_in[7];
    float* out = (float*)d_out;

    int B = in_sizes[0] / KDIM;
    int grid = (B + BLOCKT - 1) / BLOCKT;       // 1024 blocks
    size_t smem_bytes = SMEM_FLOATS * sizeof(float);  // ~31.4 KB
    cudaFuncSetAttribute(qhybrid_kernel,
                         cudaFuncAttributeMaxDynamicSharedMemorySize,
                         (int)smem_bytes);
    qhybrid_kernel<<<grid, BLOCKT, smem_bytes>>>(x, W1, b1, qw, W2, b2, W3, b3, out, B);
}